// round 3
// baseline (speedup 1.0000x reference)
#include <cuda_runtime.h>
#include <math.h>

#define B_ 4
#define S_ 1024
#define E_ 1024
#define H_ 16
#define D_ 64

// ---------------- scratch (alloc-free: __device__ globals, ~64.5 MB) -------
__device__ float g_q[B_*H_*S_*D_];          // 16 MB  [b,h,s,d]
__device__ float g_k[B_*H_*S_*D_];          // 16 MB
__device__ float g_v[B_*H_*S_*D_];          // 16 MB
__device__ float g_ctx[B_*S_*E_];           // 16 MB  [b,s,h*D+d]
__device__ float g_m[B_*H_*S_];             // row max   (post-bias scores)
__device__ float g_l[B_*H_*S_];             // row sumexp
__device__ float g_maskbias[B_*S_];         // additive 0 / -inf

// ---------------- mask dtype detection + expansion ----------------
// key_padding_mask may arrive as bool(u8), int32, or float32. Classify raw
// words: all in {0,1} -> int32; all in {0,1.0f bits} -> float32; else u8.
__global__ void mask_kernel(const void* __restrict__ mask_raw) {
    __shared__ int s_int, s_flt;
    int t = threadIdx.x;                        // 1024 threads
    if (t == 0) { s_int = 1; s_flt = 1; }
    __syncthreads();
    const unsigned int* w = (const unsigned int*)mask_raw;
    unsigned int v = w[t];                      // first 4096 bytes always valid
    if (!(v == 0u || v == 1u))           atomicAnd(&s_int, 0);
    if (!(v == 0u || v == 0x3f800000u))  atomicAnd(&s_flt, 0);
    __syncthreads();
    int mode = s_int ? 0 : (s_flt ? 1 : 2);
    for (int i = t; i < B_*S_; i += 1024) {
        bool keep;
        if (mode == 0)      keep = ((const int*)mask_raw)[i] != 0;
        else if (mode == 1) keep = ((const float*)mask_raw)[i] != 0.0f;
        else                keep = ((const unsigned char*)mask_raw)[i] != 0;
        g_maskbias[i] = keep ? 0.0f : -INFINITY;
    }
}

// ---------------- shared micro-kernel: 4x4 outer-product FMA ----------------
#define MICRO_FMA(acc, a, wv)                                                \
    acc[0][0] += a.x*wv.x; acc[0][1] += a.x*wv.y; acc[0][2] += a.x*wv.z; acc[0][3] += a.x*wv.w; \
    acc[1][0] += a.y*wv.x; acc[1][1] += a.y*wv.y; acc[1][2] += a.y*wv.z; acc[1][3] += a.y*wv.w; \
    acc[2][0] += a.z*wv.x; acc[2][1] += a.z*wv.y; acc[2][2] += a.z*wv.z; acc[2][3] += a.z*wv.w; \
    acc[3][0] += a.w*wv.x; acc[3][1] += a.w*wv.y; acc[3][2] += a.w*wv.z; acc[3][3] += a.w*wv.w;

// ---------------- K1: QKV projection  out[m,n] = A[m,:] . W[n,:] + b[n] ----
// z selects q/k/v. Writes head-major layout [b,h,s,d].
__global__ __launch_bounds__(256) void qkv_gemm(
    const float* __restrict__ qin, const float* __restrict__ kin,
    const float* __restrict__ vin, const float* __restrict__ W,
    const float* __restrict__ bias)
{
    const int K = E_;
    int z = blockIdx.z;
    const float* A  = (z == 0) ? qin : (z == 1) ? kin : vin;
    const float* Wz = W + z * E_ * E_;
    const float* bz = bias + z * E_;
    float* outp = (z == 0) ? g_q : (z == 1) ? g_k : g_v;

    __shared__ float As[16][68];
    __shared__ float Ws[16][68];
    int t = threadIdx.x;
    int tx = t & 15, ty = t >> 4;
    int m0 = blockIdx.y * 64, n0 = blockIdx.x * 64;
    int lr = t >> 2, lc = (t & 3) * 4;

    float acc[4][4] = {};
    for (int k0 = 0; k0 < K; k0 += 16) {
        float4 av = *(const float4*)(A  + (size_t)(m0 + lr) * K + k0 + lc);
        float4 wv = *(const float4*)(Wz + (size_t)(n0 + lr) * K + k0 + lc);
        As[lc+0][lr] = av.x; As[lc+1][lr] = av.y; As[lc+2][lr] = av.z; As[lc+3][lr] = av.w;
        Ws[lc+0][lr] = wv.x; Ws[lc+1][lr] = wv.y; Ws[lc+2][lr] = wv.z; Ws[lc+3][lr] = wv.w;
        __syncthreads();
        #pragma unroll
        for (int kk = 0; kk < 16; kk++) {
            float4 a = *(const float4*)&As[kk][ty*4];
            float4 w = *(const float4*)&Ws[kk][tx*4];
            MICRO_FMA(acc, a, w)
        }
        __syncthreads();
    }
    #pragma unroll
    for (int i = 0; i < 4; i++) {
        int m = m0 + ty*4 + i;
        int b = m >> 10, s = m & 1023;
        #pragma unroll
        for (int j = 0; j < 4; j++) {
            int n = n0 + tx*4 + j;
            int h = n >> 6, d = n & 63;
            outp[(((b*H_ + h)*S_ + s)*D_) + d] = acc[i][j] + bz[n];
        }
    }
}

// ---------------- K2: fused flash attention per (b,h,q-tile) ----------------
// Online softmax over k-tiles of 32. Writes g_ctx, g_m, g_l. No P in HBM.
__global__ __launch_bounds__(256) void flash_kernel() {
    int bh = blockIdx.y;
    int b = bh >> 4, h = bh & 15;
    int m0 = blockIdx.x * 64;
    const float* Q  = g_q + (size_t)bh * S_ * D_;
    const float* Kp = g_k + (size_t)bh * S_ * D_;
    const float* V  = g_v + (size_t)bh * S_ * D_;

    __shared__ float Qs[64][68];   // [d][r]   17408 B
    __shared__ float Ks[64][36];   // [d][c]    9216 B
    __shared__ float Vs[32][68];   // [k][d]    8704 B
    __shared__ float Ps[64][36];   // [r][c]    9216 B   (total 44544 < 48K)

    int t = threadIdx.x;
    int tx = t & 15, ty = t >> 4;

    // load Q tile once, transposed [d][r]
    {
        int lr = t >> 2, c0 = (t & 3) * 4;
        #pragma unroll
        for (int u = 0; u < 4; u++) {
            int cc = c0 + u*16;
            float4 q4 = *(const float4*)(Q + (m0 + lr) * D_ + cc);
            Qs[cc+0][lr] = q4.x; Qs[cc+1][lr] = q4.y;
            Qs[cc+2][lr] = q4.z; Qs[cc+3][lr] = q4.w;
        }
    }

    float acc[4][4] = {};
    float mrow[4], lrow[4];
    #pragma unroll
    for (int i = 0; i < 4; i++) { mrow[i] = -1e30f; lrow[i] = 0.0f; }

    int kr = t >> 3, kc0 = (t & 7) * 4;

    for (int kt = 0; kt < 32; kt++) {           // 32 tiles x 32 keys
        __syncthreads();                        // prior readers of Ks/Vs/Ps done
        #pragma unroll
        for (int u = 0; u < 2; u++) {
            int col = kc0 + u*32;
            float4 k4 = *(const float4*)(Kp + (size_t)(kt*32 + kr) * D_ + col);
            Ks[col+0][kr] = k4.x; Ks[col+1][kr] = k4.y;
            Ks[col+2][kr] = k4.z; Ks[col+3][kr] = k4.w;
            float4 v4 = *(const float4*)(V + (size_t)(kt*32 + kr) * D_ + col);
            *(float4*)&Vs[kr][col] = v4;
        }
        __syncthreads();

        // S tile 64x32 = Q . K^T
        float s[4][2] = {};
        #pragma unroll
        for (int dd = 0; dd < 64; dd++) {
            float4 a = *(const float4*)&Qs[dd][ty*4];
            float2 w = *(const float2*)&Ks[dd][tx*2];
            s[0][0] += a.x*w.x; s[0][1] += a.x*w.y;
            s[1][0] += a.y*w.x; s[1][1] += a.y*w.y;
            s[2][0] += a.z*w.x; s[2][1] += a.z*w.y;
            s[3][0] += a.w*w.x; s[3][1] += a.w*w.y;
        }

        // online softmax update, stash P tile
        #pragma unroll
        for (int i = 0; i < 4; i++) {
            int r = m0 + ty*4 + i;
            int c0c = kt*32 + tx*2;
            float sv0 = s[i][0]*0.125f + (float)(r - c0c)     + g_maskbias[b*S_ + c0c];
            float sv1 = s[i][1]*0.125f + (float)(r - c0c - 1) + g_maskbias[b*S_ + c0c + 1];
            float rmax = fmaxf(sv0, sv1);
            #pragma unroll
            for (int o = 8; o > 0; o >>= 1)
                rmax = fmaxf(rmax, __shfl_xor_sync(0xffffffffu, rmax, o));
            float mnew = fmaxf(mrow[i], fmaxf(rmax, -1e30f));
            float sf = __expf(mrow[i] - mnew);
            float p0 = __expf(sv0 - mnew);
            float p1 = __expf(sv1 - mnew);
            float rs = p0 + p1;
            #pragma unroll
            for (int o = 8; o > 0; o >>= 1)
                rs += __shfl_xor_sync(0xffffffffu, rs, o);
            lrow[i] = lrow[i]*sf + rs;
            mrow[i] = mnew;
            acc[i][0] *= sf; acc[i][1] *= sf; acc[i][2] *= sf; acc[i][3] *= sf;
            *(float2*)&Ps[ty*4+i][tx*2] = make_float2(p0, p1);
        }
        __syncthreads();

        // acc[r][d] += P[r][k] . V[k][d]
        #pragma unroll
        for (int kk = 0; kk < 32; kk++) {
            float4 w = *(const float4*)&Vs[kk][tx*4];
            float a0 = Ps[ty*4+0][kk];
            float a1 = Ps[ty*4+1][kk];
            float a2 = Ps[ty*4+2][kk];
            float a3 = Ps[ty*4+3][kk];
            acc[0][0]+=a0*w.x; acc[0][1]+=a0*w.y; acc[0][2]+=a0*w.z; acc[0][3]+=a0*w.w;
            acc[1][0]+=a1*w.x; acc[1][1]+=a1*w.y; acc[1][2]+=a1*w.z; acc[1][3]+=a1*w.w;
            acc[2][0]+=a2*w.x; acc[2][1]+=a2*w.y; acc[2][2]+=a2*w.z; acc[2][3]+=a2*w.w;
            acc[3][0]+=a3*w.x; acc[3][1]+=a3*w.y; acc[3][2]+=a3*w.z; acc[3][3]+=a3*w.w;
        }
    }

    // epilogue: normalize, write ctx + stats
    #pragma unroll
    for (int i = 0; i < 4; i++) {
        int r = m0 + ty*4 + i;
        float inv = 1.0f / lrow[i];
        float4 o4 = make_float4(acc[i][0]*inv, acc[i][1]*inv, acc[i][2]*inv, acc[i][3]*inv);
        *(float4*)&g_ctx[((size_t)(b*S_ + r))*E_ + h*D_ + tx*4] = o4;
        if (tx == 0) {
            g_m[(size_t)bh*S_ + r] = mrow[i];
            g_l[(size_t)bh*S_ + r] = lrow[i];
        }
    }
}

// ---------------- K3: attn_weights mean over heads (recompute scores) -------
// grid (kt=16, qt=16, b=4); block: 64 q rows x 64 k cols, loop 16 heads.
__global__ __launch_bounds__(256) void attnmean_kernel(float* __restrict__ out_attn) {
    int kt = blockIdx.x;
    int m0 = blockIdx.y * 64;
    int b  = blockIdx.z;

    __shared__ float Qs[64][68];   // [d][r]
    __shared__ float Ks[64][68];   // [d][c]
    int t = threadIdx.x;
    int tx = t & 15, ty = t >> 4;
    int lr = t >> 2, c0 = (t & 3) * 4;

    float acc[4][4] = {};
    for (int h = 0; h < H_; h++) {
        int bh = b*H_ + h;
        const float* Q  = g_q + (size_t)bh*S_*D_;
        const float* Kp = g_k + (size_t)bh*S_*D_;
        __syncthreads();
        #pragma unroll
        for (int u = 0; u < 4; u++) {
            int cc = c0 + u*16;
            float4 q4 = *(const float4*)(Q + (m0 + lr)*D_ + cc);
            Qs[cc+0][lr]=q4.x; Qs[cc+1][lr]=q4.y; Qs[cc+2][lr]=q4.z; Qs[cc+3][lr]=q4.w;
            float4 k4 = *(const float4*)(Kp + (kt*64 + lr)*D_ + cc);
            Ks[cc+0][lr]=k4.x; Ks[cc+1][lr]=k4.y; Ks[cc+2][lr]=k4.z; Ks[cc+3][lr]=k4.w;
        }
        __syncthreads();

        float s[4][4] = {};
        #pragma unroll
        for (int dd = 0; dd < 64; dd++) {
            float4 a = *(const float4*)&Qs[dd][ty*4];
            float4 w = *(const float4*)&Ks[dd][tx*4];
            MICRO_FMA(s, a, w)
        }

        #pragma unroll
        for (int i = 0; i < 4; i++) {
            int r = m0 + ty*4 + i;
            float mm  = g_m[(size_t)bh*S_ + r];
            float inv = 1.0f / g_l[(size_t)bh*S_ + r];
            #pragma unroll
            for (int j = 0; j < 4; j++) {
                int c = kt*64 + tx*4 + j;
                float sv = s[i][j]*0.125f + (float)(r - c) + g_maskbias[b*S_ + c];
                acc[i][j] += __expf(sv - mm) * inv;
            }
        }
    }
    #pragma unroll
    for (int i = 0; i < 4; i++) {
        int r = m0 + ty*4 + i;
        float4 o4 = make_float4(acc[i][0]*0.0625f, acc[i][1]*0.0625f,
                                acc[i][2]*0.0625f, acc[i][3]*0.0625f);
        *(float4*)&out_attn[((size_t)(b*S_ + r))*S_ + kt*64 + tx*4] = o4;
    }
}

// ---------------- K4: out = ctx @ Wo^T + bo ---------------------------------
__global__ __launch_bounds__(256) void out_gemm(
    const float* __restrict__ W, const float* __restrict__ bias,
    float* __restrict__ out)
{
    const int K = E_;
    __shared__ float As[16][68];
    __shared__ float Ws[16][68];
    int t = threadIdx.x;
    int tx = t & 15, ty = t >> 4;
    int m0 = blockIdx.y * 64, n0 = blockIdx.x * 64;
    int lr = t >> 2, lc = (t & 3) * 4;

    float acc[4][4] = {};
    for (int k0 = 0; k0 < K; k0 += 16) {
        float4 av = *(const float4*)(g_ctx + (size_t)(m0 + lr) * K + k0 + lc);
        float4 wv = *(const float4*)(W     + (size_t)(n0 + lr) * K + k0 + lc);
        As[lc+0][lr] = av.x; As[lc+1][lr] = av.y; As[lc+2][lr] = av.z; As[lc+3][lr] = av.w;
        Ws[lc+0][lr] = wv.x; Ws[lc+1][lr] = wv.y; Ws[lc+2][lr] = wv.z; Ws[lc+3][lr] = wv.w;
        __syncthreads();
        #pragma unroll
        for (int kk = 0; kk < 16; kk++) {
            float4 a = *(const float4*)&As[kk][ty*4];
            float4 w = *(const float4*)&Ws[kk][tx*4];
            MICRO_FMA(acc, a, w)
        }
        __syncthreads();
    }
    #pragma unroll
    for (int i = 0; i < 4; i++) {
        int m = m0 + ty*4 + i;
        #pragma unroll
        for (int j = 0; j < 4; j++) {
            int n = n0 + tx*4 + j;
            out[(size_t)m * E_ + n] = acc[i][j] + bias[n];
        }
    }
}

// ---------------- launch ----------------------------------------------------
extern "C" void kernel_launch(void* const* d_in, const int* in_sizes, int n_in,
                              void* d_out, int out_size)
{
    const float* query = (const float*)d_in[0];
    const float* key   = (const float*)d_in[1];
    const float* value = (const float*)d_in[2];
    const void*  mask  = d_in[3];
    const float* win   = (const float*)d_in[4];
    const float* bin   = (const float*)d_in[5];
    const float* wout  = (const float*)d_in[6];
    const float* bout  = (const float*)d_in[7];

    float* out      = (float*)d_out;                      // [4,1024,1024] output
    float* out_attn = out + (size_t)B_ * S_ * E_;         // [4,1024,1024] attn mean

    mask_kernel<<<1, 1024>>>(mask);
    qkv_gemm<<<dim3(16, 64, 3), 256>>>(query, key, value, win, bin);
    flash_kernel<<<dim3(16, 64), 256>>>();
    attnmean_kernel<<<dim3(16, 16, 4), 256>>>(out_attn);
    out_gemm<<<dim3(16, 64), 256>>>(wout, bout, out);
}

// round 5
// speedup vs baseline: 2.1392x; 2.1392x over previous
#include <cuda_runtime.h>
#include <math.h>

#define B_ 4
#define S_ 1024
#define E_ 1024
#define H_ 16
#define D_ 64

// ---------------- scratch (alloc-free: __device__ globals, ~64.5 MB) -------
__device__ float g_q[B_*H_*S_*D_];          // 16 MB  [b,h,s,d]
__device__ float g_k[B_*H_*S_*D_];          // 16 MB
__device__ float g_v[B_*H_*S_*D_];          // 16 MB
__device__ float g_ctx[B_*S_*E_];           // 16 MB  [b,s,h*D+d]
__device__ float g_m[B_*H_*S_];             // row max   (post-bias scores)
__device__ float g_l[B_*H_*S_];             // row sumexp
__device__ float g_maskbias[B_*S_];         // additive 0 / -inf

// ---------------- tf32 helpers ----------------
__device__ __forceinline__ unsigned f2tf(float x) {
    unsigned u; asm("cvt.rna.tf32.f32 %0, %1;" : "=r"(u) : "f"(x)); return u;
}
__device__ __forceinline__ float f2tff(float x) { return __uint_as_float(f2tf(x)); }

// D += A(16x8, row) * B(8x8, col);  c[4] fp32, a[4]/b[2] tf32 bits
__device__ __forceinline__ void mma_tf32(float* c, const unsigned* a, const unsigned* b) {
    asm volatile(
        "mma.sync.aligned.m16n8k8.row.col.f32.tf32.tf32.f32 "
        "{%0,%1,%2,%3}, {%4,%5,%6,%7}, {%8,%9}, {%0,%1,%2,%3};"
        : "+f"(c[0]), "+f"(c[1]), "+f"(c[2]), "+f"(c[3])
        : "r"(a[0]), "r"(a[1]), "r"(a[2]), "r"(a[3]), "r"(b[0]), "r"(b[1]));
}

// ---------------- mask dtype detection + expansion ----------------
__global__ void mask_kernel(const void* __restrict__ mask_raw) {
    __shared__ int s_int, s_flt;
    int t = threadIdx.x;                        // 1024 threads
    if (t == 0) { s_int = 1; s_flt = 1; }
    __syncthreads();
    const unsigned int* w = (const unsigned int*)mask_raw;
    unsigned int v = w[t];
    if (!(v == 0u || v == 1u))           atomicAnd(&s_int, 0);
    if (!(v == 0u || v == 0x3f800000u))  atomicAnd(&s_flt, 0);
    __syncthreads();
    int mode = s_int ? 0 : (s_flt ? 1 : 2);
    for (int i = t; i < B_*S_; i += 1024) {
        bool keep;
        if (mode == 0)      keep = ((const int*)mask_raw)[i] != 0;
        else if (mode == 1) keep = ((const float*)mask_raw)[i] != 0.0f;
        else                keep = ((const unsigned char*)mask_raw)[i] != 0;
        g_maskbias[i] = keep ? 0.0f : -INFINITY;
    }
}

// ---------------- K1: QKV projection (tf32 mma) -----------------------------
// C[m,n] = A[m,:] . W[n,:]^T + b[n]; BM=128 BN=64 BK=32; 8 warps (4m x 2n).
__global__ __launch_bounds__(256) void qkv_gemm(
    const float* __restrict__ qin, const float* __restrict__ kin,
    const float* __restrict__ vin, const float* __restrict__ W,
    const float* __restrict__ bias)
{
    int z = blockIdx.z;
    const float* A  = (z == 0) ? qin : (z == 1) ? kin : vin;
    const float* Wz = W + z * E_ * E_;
    const float* bz = bias + z * E_;
    float* outp = (z == 0) ? g_q : (z == 1) ? g_k : g_v;

    __shared__ float As[128][36];
    __shared__ float Ws[64][36];
    int t = threadIdx.x, w = t >> 5, lane = t & 31, g = lane >> 2, tig = lane & 3;
    int wm = (w & 3) * 32, wn = (w >> 2) * 32;
    int m0 = blockIdx.y * 128, n0 = blockIdx.x * 64;

    float acc[2][4][4] = {};
    int ar = t >> 3, ac = (t & 7) * 4;      // A: 32 rows/pass x 8 f4 cols
    int wr = t >> 2, wc = (t & 3) * 8;      // W: 64 rows x 2 f4 each

    for (int k0 = 0; k0 < E_; k0 += 32) {
        #pragma unroll
        for (int p = 0; p < 4; p++) {
            float4 v = *(const float4*)(A + (size_t)(m0 + ar + p*32) * E_ + k0 + ac);
            As[ar + p*32][ac+0] = f2tff(v.x); As[ar + p*32][ac+1] = f2tff(v.y);
            As[ar + p*32][ac+2] = f2tff(v.z); As[ar + p*32][ac+3] = f2tff(v.w);
        }
        {
            float4 v0 = *(const float4*)(Wz + (size_t)(n0 + wr) * E_ + k0 + wc);
            float4 v1 = *(const float4*)(Wz + (size_t)(n0 + wr) * E_ + k0 + wc + 4);
            Ws[wr][wc+0] = f2tff(v0.x); Ws[wr][wc+1] = f2tff(v0.y);
            Ws[wr][wc+2] = f2tff(v0.z); Ws[wr][wc+3] = f2tff(v0.w);
            Ws[wr][wc+4] = f2tff(v1.x); Ws[wr][wc+5] = f2tff(v1.y);
            Ws[wr][wc+6] = f2tff(v1.z); Ws[wr][wc+7] = f2tff(v1.w);
        }
        __syncthreads();
        #pragma unroll
        for (int ks = 0; ks < 4; ks++) {
            unsigned a[2][4], bf[4][2];
            #pragma unroll
            for (int mt = 0; mt < 2; mt++) {
                int r = wm + mt*16 + g, k = ks*8 + tig;
                a[mt][0] = __float_as_uint(As[r  ][k  ]);
                a[mt][1] = __float_as_uint(As[r+8][k  ]);
                a[mt][2] = __float_as_uint(As[r  ][k+4]);
                a[mt][3] = __float_as_uint(As[r+8][k+4]);
            }
            #pragma unroll
            for (int nt = 0; nt < 4; nt++) {
                int n = wn + nt*8 + g, k = ks*8 + tig;
                bf[nt][0] = __float_as_uint(Ws[n][k  ]);
                bf[nt][1] = __float_as_uint(Ws[n][k+4]);
            }
            #pragma unroll
            for (int mt = 0; mt < 2; mt++)
                #pragma unroll
                for (int nt = 0; nt < 4; nt++)
                    mma_tf32(acc[mt][nt], a[mt], bf[nt]);
        }
        __syncthreads();
    }
    #pragma unroll
    for (int mt = 0; mt < 2; mt++) {
        int m_ = m0 + wm + mt*16 + g;
        int bb = m_ >> 10, s0 = m_ & 1023;
        #pragma unroll
        for (int nt = 0; nt < 4; nt++) {
            int n_ = n0 + wn + nt*8 + tig*2;
            int h = n_ >> 6, d = n_ & 63;
            float bx = bz[n_], by = bz[n_+1];
            *(float2*)&outp[(((bb*H_ + h)*S_ + s0    )*D_) + d] =
                make_float2(acc[mt][nt][0] + bx, acc[mt][nt][1] + by);
            *(float2*)&outp[(((bb*H_ + h)*S_ + s0 + 8)*D_) + d] =
                make_float2(acc[mt][nt][2] + bx, acc[mt][nt][3] + by);
        }
    }
}

// ---------------- K2: fused flash attention (tf32 mma), 4 warps -------------
__global__ __launch_bounds__(128) void flash_kernel() {
    int bh = blockIdx.y; int b = bh >> 4, h = bh & 15;
    int m0 = blockIdx.x * 64;
    const float* Q  = g_q + (size_t)bh * S_ * D_;
    const float* Kp = g_k + (size_t)bh * S_ * D_;
    const float* V  = g_v + (size_t)bh * S_ * D_;
    const float* mb = g_maskbias + b * S_;

    __shared__ float Qs[64][68];
    __shared__ float Ks[32][68];
    __shared__ float Vs[32][68];
    __shared__ float Ps[64][36];

    int t = threadIdx.x, w = t >> 5, lane = t & 31, g = lane >> 2, tig = lane & 3;
    int wm = w * 16;
    int r_lo = m0 + wm + g, r_hi = r_lo + 8;

    {   // Q tile -> smem (tf32), row-major [64][64]
        int r = t >> 1, c0 = (t & 1) * 32;
        #pragma unroll
        for (int j = 0; j < 8; j++) {
            float4 v = *(const float4*)(Q + (size_t)(m0 + r) * D_ + c0 + j*4);
            Qs[r][c0+j*4+0] = f2tff(v.x); Qs[r][c0+j*4+1] = f2tff(v.y);
            Qs[r][c0+j*4+2] = f2tff(v.z); Qs[r][c0+j*4+3] = f2tff(v.w);
        }
    }

    float acc[8][4] = {};
    float mlo = -1e30f, mhi = -1e30f, llo = 0.0f, lhi = 0.0f;

    for (int kt = 0; kt < 32; kt++) {
        __syncthreads();
        {   // K,V tiles 32x64 -> smem (tf32)
            int kr = t >> 2, c0 = (t & 3) * 16;
            #pragma unroll
            for (int j = 0; j < 4; j++) {
                float4 kv = *(const float4*)(Kp + (size_t)(kt*32 + kr) * D_ + c0 + j*4);
                Ks[kr][c0+j*4+0] = f2tff(kv.x); Ks[kr][c0+j*4+1] = f2tff(kv.y);
                Ks[kr][c0+j*4+2] = f2tff(kv.z); Ks[kr][c0+j*4+3] = f2tff(kv.w);
                float4 vv = *(const float4*)(V + (size_t)(kt*32 + kr) * D_ + c0 + j*4);
                Vs[kr][c0+j*4+0] = f2tff(vv.x); Vs[kr][c0+j*4+1] = f2tff(vv.y);
                Vs[kr][c0+j*4+2] = f2tff(vv.z); Vs[kr][c0+j*4+3] = f2tff(vv.w);
            }
        }
        __syncthreads();

        // S(16x32 per warp) = Q . K^T
        float s[4][4] = {};
        #pragma unroll
        for (int ks = 0; ks < 8; ks++) {
            int k = ks*8 + tig;
            unsigned a[4];
            a[0] = __float_as_uint(Qs[wm+g  ][k  ]);
            a[1] = __float_as_uint(Qs[wm+g+8][k  ]);
            a[2] = __float_as_uint(Qs[wm+g  ][k+4]);
            a[3] = __float_as_uint(Qs[wm+g+8][k+4]);
            #pragma unroll
            for (int nt = 0; nt < 4; nt++) {
                unsigned bf[2];
                bf[0] = __float_as_uint(Ks[nt*8+g][k  ]);
                bf[1] = __float_as_uint(Ks[nt*8+g][k+4]);
                mma_tf32(s[nt], a, bf);
            }
        }

        // scale + rel bias + mask, then online softmax
        float rml = -1e30f, rmh = -1e30f;
        #pragma unroll
        for (int nt = 0; nt < 4; nt++) {
            int c = kt*32 + nt*8 + tig*2;
            float mb0 = mb[c], mb1 = mb[c+1];
            s[nt][0] = s[nt][0]*0.125f + (float)(r_lo - c    ) + mb0;
            s[nt][1] = s[nt][1]*0.125f + (float)(r_lo - c - 1) + mb1;
            s[nt][2] = s[nt][2]*0.125f + (float)(r_hi - c    ) + mb0;
            s[nt][3] = s[nt][3]*0.125f + (float)(r_hi - c - 1) + mb1;
            rml = fmaxf(rml, fmaxf(s[nt][0], s[nt][1]));
            rmh = fmaxf(rmh, fmaxf(s[nt][2], s[nt][3]));
        }
        rml = fmaxf(rml, __shfl_xor_sync(0xffffffffu, rml, 1));
        rml = fmaxf(rml, __shfl_xor_sync(0xffffffffu, rml, 2));
        rmh = fmaxf(rmh, __shfl_xor_sync(0xffffffffu, rmh, 1));
        rmh = fmaxf(rmh, __shfl_xor_sync(0xffffffffu, rmh, 2));

        float mnl = fmaxf(mlo, rml), mnh = fmaxf(mhi, rmh);
        float sfl = __expf(mlo - mnl), sfh = __expf(mhi - mnh);
        float rsl = 0.0f, rsh = 0.0f;
        #pragma unroll
        for (int nt = 0; nt < 4; nt++) {
            float p0 = __expf(s[nt][0] - mnl), p1 = __expf(s[nt][1] - mnl);
            float p2 = __expf(s[nt][2] - mnh), p3 = __expf(s[nt][3] - mnh);
            rsl += p0 + p1; rsh += p2 + p3;
            int c = nt*8 + tig*2;
            Ps[wm+g  ][c] = f2tff(p0); Ps[wm+g  ][c+1] = f2tff(p1);
            Ps[wm+g+8][c] = f2tff(p2); Ps[wm+g+8][c+1] = f2tff(p3);
        }
        rsl += __shfl_xor_sync(0xffffffffu, rsl, 1);
        rsl += __shfl_xor_sync(0xffffffffu, rsl, 2);
        rsh += __shfl_xor_sync(0xffffffffu, rsh, 1);
        rsh += __shfl_xor_sync(0xffffffffu, rsh, 2);
        llo = llo*sfl + rsl; lhi = lhi*sfh + rsh;
        mlo = mnl; mhi = mnh;
        #pragma unroll
        for (int nt = 0; nt < 8; nt++) {
            acc[nt][0] *= sfl; acc[nt][1] *= sfl;
            acc[nt][2] *= sfh; acc[nt][3] *= sfh;
        }
        __syncwarp();   // P rows are warp-local; Vs already block-synced

        // acc(16x64) += P(16x32) . V(32x64)
        #pragma unroll
        for (int ks = 0; ks < 4; ks++) {
            int k = ks*8 + tig;
            unsigned a[4];
            a[0] = __float_as_uint(Ps[wm+g  ][k  ]);
            a[1] = __float_as_uint(Ps[wm+g+8][k  ]);
            a[2] = __float_as_uint(Ps[wm+g  ][k+4]);
            a[3] = __float_as_uint(Ps[wm+g+8][k+4]);
            #pragma unroll
            for (int nt = 0; nt < 8; nt++) {
                unsigned bf[2];
                bf[0] = __float_as_uint(Vs[k  ][nt*8+g]);
                bf[1] = __float_as_uint(Vs[k+4][nt*8+g]);
                mma_tf32(acc[nt], a, bf);
            }
        }
    }

    float il = 1.0f / llo, ih = 1.0f / lhi;
    float* clo = &g_ctx[((size_t)(b*S_ + r_lo))*E_ + h*D_];
    float* chi = &g_ctx[((size_t)(b*S_ + r_hi))*E_ + h*D_];
    #pragma unroll
    for (int nt = 0; nt < 8; nt++) {
        int d = nt*8 + tig*2;
        *(float2*)&clo[d] = make_float2(acc[nt][0]*il, acc[nt][1]*il);
        *(float2*)&chi[d] = make_float2(acc[nt][2]*ih, acc[nt][3]*ih);
    }
    if (tig == 0) {
        g_m[(size_t)bh*S_ + r_lo] = mlo; g_l[(size_t)bh*S_ + r_lo] = llo;
        g_m[(size_t)bh*S_ + r_hi] = mhi; g_l[(size_t)bh*S_ + r_hi] = lhi;
    }
}

// ---------------- K3: attn mean over heads (tf32 mma recompute) -------------
__global__ __launch_bounds__(128) void attnmean_kernel(float* __restrict__ out_attn) {
    int kt = blockIdx.x, m0 = blockIdx.y * 64, b = blockIdx.z;
    __shared__ float Qs[64][68];
    __shared__ float Ks[64][68];
    int t = threadIdx.x, w = t >> 5, lane = t & 31, g = lane >> 2, tig = lane & 3;
    int wm = w * 16;
    int r_lo = m0 + wm + g, r_hi = r_lo + 8;
    const float* mb = g_maskbias + b * S_;

    float acc[8][4] = {};
    for (int h = 0; h < H_; h++) {
        int bh = b*H_ + h;
        const float* Q  = g_q + (size_t)bh * S_ * D_;
        const float* Kp = g_k + (size_t)bh * S_ * D_ + (size_t)kt * 64 * D_;
        __syncthreads();
        {
            int r = t >> 1, c0 = (t & 1) * 32;
            #pragma unroll
            for (int j = 0; j < 8; j++) {
                float4 qv = *(const float4*)(Q + (size_t)(m0 + r) * D_ + c0 + j*4);
                Qs[r][c0+j*4+0] = f2tff(qv.x); Qs[r][c0+j*4+1] = f2tff(qv.y);
                Qs[r][c0+j*4+2] = f2tff(qv.z); Qs[r][c0+j*4+3] = f2tff(qv.w);
                float4 kv = *(const float4*)(Kp + (size_t)r * D_ + c0 + j*4);
                Ks[r][c0+j*4+0] = f2tff(kv.x); Ks[r][c0+j*4+1] = f2tff(kv.y);
                Ks[r][c0+j*4+2] = f2tff(kv.z); Ks[r][c0+j*4+3] = f2tff(kv.w);
            }
        }
        __syncthreads();

        float s[8][4] = {};
        #pragma unroll
        for (int ks = 0; ks < 8; ks++) {
            int k = ks*8 + tig;
            unsigned a[4];
            a[0] = __float_as_uint(Qs[wm+g  ][k  ]);
            a[1] = __float_as_uint(Qs[wm+g+8][k  ]);
            a[2] = __float_as_uint(Qs[wm+g  ][k+4]);
            a[3] = __float_as_uint(Qs[wm+g+8][k+4]);
            #pragma unroll
            for (int nt = 0; nt < 8; nt++) {
                unsigned bf[2];
                bf[0] = __float_as_uint(Ks[nt*8+g][k  ]);
                bf[1] = __float_as_uint(Ks[nt*8+g][k+4]);
                mma_tf32(s[nt], a, bf);
            }
        }

        float ml = g_m[(size_t)bh*S_ + r_lo], il = 1.0f / g_l[(size_t)bh*S_ + r_lo];
        float mh = g_m[(size_t)bh*S_ + r_hi], ih = 1.0f / g_l[(size_t)bh*S_ + r_hi];
        #pragma unroll
        for (int nt = 0; nt < 8; nt++) {
            int c = kt*64 + nt*8 + tig*2;
            float mb0 = mb[c], mb1 = mb[c+1];
            acc[nt][0] += __expf(s[nt][0]*0.125f + (float)(r_lo - c    ) + mb0 - ml) * il;
            acc[nt][1] += __expf(s[nt][1]*0.125f + (float)(r_lo - c - 1) + mb1 - ml) * il;
            acc[nt][2] += __expf(s[nt][2]*0.125f + (float)(r_hi - c    ) + mb0 - mh) * ih;
            acc[nt][3] += __expf(s[nt][3]*0.125f + (float)(r_hi - c - 1) + mb1 - mh) * ih;
        }
    }
    float* olo = &out_attn[((size_t)(b*S_ + r_lo))*S_ + kt*64];
    float* ohi = &out_attn[((size_t)(b*S_ + r_hi))*S_ + kt*64];
    #pragma unroll
    for (int nt = 0; nt < 8; nt++) {
        int c = nt*8 + tig*2;
        *(float2*)&olo[c] = make_float2(acc[nt][0]*0.0625f, acc[nt][1]*0.0625f);
        *(float2*)&ohi[c] = make_float2(acc[nt][2]*0.0625f, acc[nt][3]*0.0625f);
    }
}

// ---------------- K4: out = ctx @ Wo^T + bo (tf32 mma) ----------------------
__global__ __launch_bounds__(256) void out_gemm(
    const float* __restrict__ W, const float* __restrict__ bias,
    float* __restrict__ out)
{
    __shared__ float As[128][36];
    __shared__ float Ws[64][36];
    int t = threadIdx.x, w = t >> 5, lane = t & 31, g = lane >> 2, tig = lane & 3;
    int wm = (w & 3) * 32, wn = (w >> 2) * 32;
    int m0 = blockIdx.y * 128, n0 = blockIdx.x * 64;

    float acc[2][4][4] = {};
    int ar = t >> 3, ac = (t & 7) * 4;
    int wr = t >> 2, wc = (t & 3) * 8;

    for (int k0 = 0; k0 < E_; k0 += 32) {
        #pragma unroll
        for (int p = 0; p < 4; p++) {
            float4 v = *(const float4*)(g_ctx + (size_t)(m0 + ar + p*32) * E_ + k0 + ac);
            As[ar + p*32][ac+0] = f2tff(v.x); As[ar + p*32][ac+1] = f2tff(v.y);
            As[ar + p*32][ac+2] = f2tff(v.z); As[ar + p*32][ac+3] = f2tff(v.w);
        }
        {
            float4 v0 = *(const float4*)(W + (size_t)(n0 + wr) * E_ + k0 + wc);
            float4 v1 = *(const float4*)(W + (size_t)(n0 + wr) * E_ + k0 + wc + 4);
            Ws[wr][wc+0] = f2tff(v0.x); Ws[wr][wc+1] = f2tff(v0.y);
            Ws[wr][wc+2] = f2tff(v0.z); Ws[wr][wc+3] = f2tff(v0.w);
            Ws[wr][wc+4] = f2tff(v1.x); Ws[wr][wc+5] = f2tff(v1.y);
            Ws[wr][wc+6] = f2tff(v1.z); Ws[wr][wc+7] = f2tff(v1.w);
        }
        __syncthreads();
        #pragma unroll
        for (int ks = 0; ks < 4; ks++) {
            unsigned a[2][4], bf[4][2];
            #pragma unroll
            for (int mt = 0; mt < 2; mt++) {
                int r = wm + mt*16 + g, k = ks*8 + tig;
                a[mt][0] = __float_as_uint(As[r  ][k  ]);
                a[mt][1] = __float_as_uint(As[r+8][k  ]);
                a[mt][2] = __float_as_uint(As[r  ][k+4]);
                a[mt][3] = __float_as_uint(As[r+8][k+4]);
            }
            #pragma unroll
            for (int nt = 0; nt < 4; nt++) {
                int n = wn + nt*8 + g, k = ks*8 + tig;
                bf[nt][0] = __float_as_uint(Ws[n][k  ]);
                bf[nt][1] = __float_as_uint(Ws[n][k+4]);
            }
            #pragma unroll
            for (int mt = 0; mt < 2; mt++)
                #pragma unroll
                for (int nt = 0; nt < 4; nt++)
                    mma_tf32(acc[mt][nt], a[mt], bf[nt]);
        }
        __syncthreads();
    }
    #pragma unroll
    for (int mt = 0; mt < 2; mt++) {
        int m_ = m0 + wm + mt*16 + g;
        #pragma unroll
        for (int nt = 0; nt < 4; nt++) {
            int n_ = n0 + wn + nt*8 + tig*2;
            float bx = bias[n_], by = bias[n_+1];
            *(float2*)&out[(size_t)m_ * E_ + n_] =
                make_float2(acc[mt][nt][0] + bx, acc[mt][nt][1] + by);
            *(float2*)&out[(size_t)(m_+8) * E_ + n_] =
                make_float2(acc[mt][nt][2] + bx, acc[mt][nt][3] + by);
        }
    }
}

// ---------------- launch ----------------------------------------------------
extern "C" void kernel_launch(void* const* d_in, const int* in_sizes, int n_in,
                              void* d_out, int out_size)
{
    const float* query = (const float*)d_in[0];
    const float* key   = (const float*)d_in[1];
    const float* value = (const float*)d_in[2];
    const void*  mask  = d_in[3];
    const float* win   = (const float*)d_in[4];
    const float* bin   = (const float*)d_in[5];
    const float* wout  = (const float*)d_in[6];
    const float* bout  = (const float*)d_in[7];

    float* out      = (float*)d_out;                      // [4,1024,1024] output
    float* out_attn = out + (size_t)B_ * S_ * E_;         // [4,1024,1024] attn mean

    mask_kernel<<<1, 1024>>>(mask);
    qkv_gemm<<<dim3(16, 32, 3), 256>>>(query, key, value, win, bin);
    flash_kernel<<<dim3(16, 64), 128>>>();
    attnmean_kernel<<<dim3(16, 16, 4), 128>>>(out_attn);
    out_gemm<<<dim3(16, 32), 256>>>(wout, bout, out);
}